// round 2
// baseline (speedup 1.0000x reference)
#include <cuda_runtime.h>
#include <cuda_bf16.h>

#define D_     512
#define NH_    8
#define HD_    64
#define NL_    6
#define DFF_   2048
#define VOCAB  1027
#define PAD_ID 1026
#define B_     256
#define SENC_  16
#define L_     61
#define NTOK   (B_ * L_)   // 15616 = 122 * 128

// ---------------- device scratch (no cudaMalloc allowed) ----------------
__device__ float g_x[NTOK * D_];          // residual stream
__device__ float g_t[NTOK * D_];          // gemm output scratch
__device__ float g_qkv[NTOK * 3 * D_];    // qkv
__device__ float g_h[(size_t)NTOK * DFF_];// ffn hidden (also attn-out scratch)
__device__ float g_vmem[B_ * D_];
__device__ float g_yca[B_ * D_];
__device__ float g_padmask[NTOK];

// ---------------- embedding + mask ----------------
__global__ void embed_kernel(const float* __restrict__ emb,
                             const float* __restrict__ point,
                             const float* __restrict__ pos,
                             const int*   __restrict__ tgt,
                             float* __restrict__ x,
                             float* __restrict__ padmask) {
    int n = blockIdx.x;
    int b = n / L_, l = n % L_;
    int tok = tgt[b * (L_ + 1) + l];
    if (threadIdx.x == 0) padmask[n] = (tok == PAD_ID) ? -1e30f : 0.0f;
    int t = threadIdx.x;  // 128 threads, D/4 = 128 float4
    float4 e  = ((const float4*)(emb   + (size_t)tok * D_))[t];
    float4 p  = ((const float4*)(point + (size_t)b   * D_))[t];
    float4 ps = ((const float4*)(pos   + (size_t)l   * D_))[t];
    float4 o;
    o.x = e.x + p.x + ps.x; o.y = e.y + p.y + ps.y;
    o.z = e.z + p.z + ps.z; o.w = e.w + p.w + ps.w;
    ((float4*)(x + (size_t)n * D_))[t] = o;
}

// ---------------- SGEMM: C[N,M] = A[N,K] @ W[M,K]^T + bias, optional relu --------
// 128x128 block tile, BK=8, 256 threads, 8x8 microtile.
// Requires N % 128 == 0 (true for all call sites: 15616, 256). M may be ragged.
__global__ __launch_bounds__(256) void sgemm_nt(
    int N, int M, int K, int lda,
    const float* __restrict__ A, const float* __restrict__ W,
    const float* __restrict__ bias, float* __restrict__ C, int relu)
{
    __shared__ float As[8][128];
    __shared__ float Bs[8][128];
    const int bm = blockIdx.y * 128;
    const int bn = blockIdx.x * 128;
    const int tid = threadIdx.x;
    const int lrow = tid >> 1;          // 0..127
    const int lcol = (tid & 1) * 4;     // 0 or 4
    const int tx = tid & 15;
    const int ty = tid >> 4;

    float acc[8][8];
#pragma unroll
    for (int i = 0; i < 8; i++)
#pragma unroll
        for (int j = 0; j < 8; j++) acc[i][j] = 0.f;

    const float* Aptr = A + (size_t)(bm + lrow) * lda + lcol;
    const bool wok = (bn + lrow) < M;
    const float* Wptr = W + (size_t)(wok ? (bn + lrow) : 0) * K + lcol;

    for (int ko = 0; ko < K; ko += 8) {
        float4 a4 = *(const float4*)(Aptr + ko);
        float4 b4 = wok ? *(const float4*)(Wptr + ko) : make_float4(0.f, 0.f, 0.f, 0.f);
        As[lcol + 0][lrow] = a4.x; As[lcol + 1][lrow] = a4.y;
        As[lcol + 2][lrow] = a4.z; As[lcol + 3][lrow] = a4.w;
        Bs[lcol + 0][lrow] = b4.x; Bs[lcol + 1][lrow] = b4.y;
        Bs[lcol + 2][lrow] = b4.z; Bs[lcol + 3][lrow] = b4.w;
        __syncthreads();
#pragma unroll
        for (int k = 0; k < 8; k++) {
            float ar[8], br[8];
#pragma unroll
            for (int i = 0; i < 4; i++) {
                ar[i]     = As[k][ty * 4 + i];
                ar[i + 4] = As[k][64 + ty * 4 + i];
            }
#pragma unroll
            for (int j = 0; j < 4; j++) {
                br[j]     = Bs[k][tx * 4 + j];
                br[j + 4] = Bs[k][64 + tx * 4 + j];
            }
#pragma unroll
            for (int i = 0; i < 8; i++)
#pragma unroll
                for (int j = 0; j < 8; j++) acc[i][j] += ar[i] * br[j];
        }
        __syncthreads();
    }
#pragma unroll
    for (int i = 0; i < 8; i++) {
        int row = bm + ((i < 4) ? (ty * 4 + i) : (64 + ty * 4 + i - 4));
#pragma unroll
        for (int j = 0; j < 8; j++) {
            int col = bn + ((j < 4) ? (tx * 4 + j) : (64 + tx * 4 + j - 4));
            if (col < M) {
                float v = acc[i][j] + (bias ? bias[col] : 0.f);
                if (relu) v = fmaxf(v, 0.f);
                C[(size_t)row * M + col] = v;
            }
        }
    }
}

// ---------------- causal self-attention, one block per (b, h) ----------------
__global__ __launch_bounds__(64) void attn_kernel(const float* __restrict__ qkv,
                            const float* __restrict__ padmask,
                            float* __restrict__ o) {
    __shared__ float ks[L_][HD_];
    __shared__ float vs[L_][HD_];
    int b = blockIdx.x / NH_, h = blockIdx.x % NH_;
    const float* base = qkv + (size_t)b * L_ * (3 * D_) + h * HD_;
    for (int idx = threadIdx.x; idx < L_ * HD_; idx += 64) {
        int l = idx >> 6, d = idx & 63;
        ks[l][d] = base[(size_t)l * (3 * D_) + D_ + d];
        vs[l][d] = base[(size_t)l * (3 * D_) + 2 * D_ + d];
    }
    __syncthreads();
    int q = threadIdx.x;
    if (q >= L_) return;
    float qr[HD_];
    const float* qrow = base + (size_t)q * (3 * D_);
#pragma unroll
    for (int d = 0; d < HD_; d++) qr[d] = qrow[d];
    float m = -1e30f, lsum = 0.f;
    float acc[HD_];
#pragma unroll
    for (int d = 0; d < HD_; d++) acc[d] = 0.f;
    const float* pm = padmask + b * L_;
    for (int k = 0; k <= q; k++) {
        float s = 0.f;
#pragma unroll
        for (int d = 0; d < HD_; d++) s += qr[d] * ks[k][d];
        s = s * 0.125f + pm[k];
        float mn = fmaxf(m, s);
        float corr = expf(m - mn);
        float e = expf(s - mn);
        lsum = lsum * corr + e;
#pragma unroll
        for (int d = 0; d < HD_; d++) acc[d] = acc[d] * corr + e * vs[k][d];
        m = mn;
    }
    float inv = 1.0f / lsum;
    float* orow = o + (size_t)(b * L_ + q) * D_ + h * HD_;
#pragma unroll
    for (int d = 0; d < HD_; d++) orow[d] = acc[d] * inv;
}

// ---------------- fused residual add + LayerNorm ----------------
// x = LN(x + y) * s + b ; y row index is n (ybatch=0) or n/L (ybatch=1, broadcast per batch)
__global__ __launch_bounds__(128) void add_ln_kernel(
                              float* __restrict__ x, const float* __restrict__ y, int ybatch,
                              const float* __restrict__ s, const float* __restrict__ b) {
    int n = blockIdx.x;
    float* xr = x + (size_t)n * D_;
    const float* yr = y + (size_t)(ybatch ? (n / L_) : n) * D_;
    int t = threadIdx.x;  // 128
    float4 xv = ((const float4*)xr)[t];
    float4 yv = ((const float4*)yr)[t];
    float v0 = xv.x + yv.x, v1 = xv.y + yv.y, v2 = xv.z + yv.z, v3 = xv.w + yv.w;
    float sum = v0 + v1 + v2 + v3;
    float sq  = v0 * v0 + v1 * v1 + v2 * v2 + v3 * v3;
#pragma unroll
    for (int off = 16; off > 0; off >>= 1) {
        sum += __shfl_xor_sync(0xffffffffu, sum, off);
        sq  += __shfl_xor_sync(0xffffffffu, sq,  off);
    }
    __shared__ float rs[4], rq[4];
    int wid = t >> 5, lane = t & 31;
    if (lane == 0) { rs[wid] = sum; rq[wid] = sq; }
    __syncthreads();
    sum = rs[0] + rs[1] + rs[2] + rs[3];
    sq  = rq[0] + rq[1] + rq[2] + rq[3];
    float mean = sum * (1.0f / D_);
    float var  = sq  * (1.0f / D_) - mean * mean;
    float rstd = rsqrtf(var + 1e-5f);
    float4 sv = ((const float4*)s)[t];
    float4 bv = ((const float4*)b)[t];
    float4 o;
    o.x = (v0 - mean) * rstd * sv.x + bv.x;
    o.y = (v1 - mean) * rstd * sv.y + bv.y;
    o.z = (v2 - mean) * rstd * sv.z + bv.z;
    o.w = (v3 - mean) * rstd * sv.w + bv.w;
    ((float4*)xr)[t] = o;
}

// ---------------- launch ----------------
extern "C" void kernel_launch(void* const* d_in, const int* in_sizes, int n_in,
                              void* d_out, int out_size) {
    const float* encoder_out = (const float*)d_in[0];
    const float* point_out   = (const float*)d_in[1];
    const float* emb         = (const float*)d_in[2];
    const float* pos_embed   = (const float*)d_in[3];
    const float* sa_inw      = (const float*)d_in[4];
    const float* sa_inb      = (const float*)d_in[5];
    const float* sa_outw     = (const float*)d_in[6];
    const float* sa_outb     = (const float*)d_in[7];
    const float* ca_inw      = (const float*)d_in[8];
    const float* ca_inb      = (const float*)d_in[9];
    const float* ca_outw     = (const float*)d_in[10];
    const float* ca_outb     = (const float*)d_in[11];
    const float* ln1_s       = (const float*)d_in[12];
    const float* ln1_b       = (const float*)d_in[13];
    const float* ln2_s       = (const float*)d_in[14];
    const float* ln2_b       = (const float*)d_in[15];
    const float* ln3_s       = (const float*)d_in[16];
    const float* ln3_b       = (const float*)d_in[17];
    const float* ff1_w       = (const float*)d_in[18];
    const float* ff1_b       = (const float*)d_in[19];
    const float* ff2_w       = (const float*)d_in[20];
    const float* ff2_b       = (const float*)d_in[21];
    const float* out_w       = (const float*)d_in[22];
    const float* out_b       = (const float*)d_in[23];
    const int*   tgt         = (const int*)d_in[24];

    float *x, *t, *qkv, *h, *vmem, *yca, *pm;
    cudaGetSymbolAddress((void**)&x,    g_x);
    cudaGetSymbolAddress((void**)&t,    g_t);
    cudaGetSymbolAddress((void**)&qkv,  g_qkv);
    cudaGetSymbolAddress((void**)&h,    g_h);
    cudaGetSymbolAddress((void**)&vmem, g_vmem);
    cudaGetSymbolAddress((void**)&yca,  g_yca);
    cudaGetSymbolAddress((void**)&pm,   g_padmask);

    const int GY = NTOK / 128;  // 122

    embed_kernel<<<NTOK, 128>>>(emb, point_out, pos_embed, tgt, x, pm);

    for (int i = 0; i < NL_; i++) {
        const float* sa_w_i   = sa_inw  + (size_t)i * 3 * D_ * D_;
        const float* sa_b_i   = sa_inb  + (size_t)i * 3 * D_;
        const float* sa_ow_i  = sa_outw + (size_t)i * D_ * D_;
        const float* sa_ob_i  = sa_outb + (size_t)i * D_;
        const float* ca_wv_i  = ca_inw  + (size_t)i * 3 * D_ * D_ + (size_t)2 * D_ * D_;
        const float* ca_bv_i  = ca_inb  + (size_t)i * 3 * D_ + 2 * D_;
        const float* ca_ow_i  = ca_outw + (size_t)i * D_ * D_;
        const float* ca_ob_i  = ca_outb + (size_t)i * D_;
        const float* f1w_i    = ff1_w   + (size_t)i * DFF_ * D_;
        const float* f1b_i    = ff1_b   + (size_t)i * DFF_;
        const float* f2w_i    = ff2_w   + (size_t)i * D_ * DFF_;
        const float* f2b_i    = ff2_b   + (size_t)i * D_;

        // ---- self attention ----
        sgemm_nt<<<dim3(12, GY), 256>>>(NTOK, 3 * D_, D_, D_, x, sa_w_i, sa_b_i, qkv, 0);
        attn_kernel<<<B_ * NH_, 64>>>(qkv, pm, h);
        sgemm_nt<<<dim3(4, GY), 256>>>(NTOK, D_, D_, D_, h, sa_ow_i, sa_ob_i, t, 0);
        add_ln_kernel<<<NTOK, 128>>>(x, t, 0, ln1_s + i * D_, ln1_b + i * D_);

        // ---- cross attention (single memory token -> output is V(mem) @ Wout + b,
        //      constant over query positions; Q/K projections provably irrelevant) ----
        sgemm_nt<<<dim3(4, 2), 256>>>(B_, D_, D_, SENC_ * D_, encoder_out, ca_wv_i, ca_bv_i, vmem, 0);
        sgemm_nt<<<dim3(4, 2), 256>>>(B_, D_, D_, D_, vmem, ca_ow_i, ca_ob_i, yca, 0);
        add_ln_kernel<<<NTOK, 128>>>(x, yca, 1, ln2_s + i * D_, ln2_b + i * D_);

        // ---- FFN ----
        sgemm_nt<<<dim3(16, GY), 256>>>(NTOK, DFF_, D_, D_, x, f1w_i, f1b_i, h, 1);
        sgemm_nt<<<dim3(4, GY), 256>>>(NTOK, D_, DFF_, DFF_, h, f2w_i, f2b_i, t, 0);
        add_ln_kernel<<<NTOK, 128>>>(x, t, 0, ln3_s + i * D_, ln3_b + i * D_);
    }

    // ---- final logits ----
    sgemm_nt<<<dim3((VOCAB + 127) / 128, GY), 256>>>(NTOK, VOCAB, D_, D_, x, out_w, out_b,
                                                     (float*)d_out, 0);
}

// round 4
// speedup vs baseline: 1.8062x; 1.8062x over previous
#include <cuda_runtime.h>
#include <cuda_bf16.h>
#include <cstdint>

#define D_     512
#define NH_    8
#define HD_    64
#define NL_    6
#define DFF_   2048
#define VOCAB  1027
#define PAD_ID 1026
#define B_     256
#define SENC_  16
#define L_     61
#define NTOK   (B_ * L_)   // 15616 = 122 * 128

// ---------------- device scratch (no cudaMalloc allowed) ----------------
__device__ float g_x[NTOK * D_];          // residual stream
__device__ float g_t[NTOK * D_];          // gemm output scratch
__device__ float g_qkv[NTOK * 3 * D_];    // qkv
__device__ float g_h[(size_t)NTOK * DFF_];// ffn hidden (also attn-out scratch)
__device__ float g_vmem[B_ * D_];
__device__ float g_yca[B_ * D_];
__device__ float g_padmask[NTOK];

// ---------------- embedding + mask ----------------
__global__ void embed_kernel(const float* __restrict__ emb,
                             const float* __restrict__ point,
                             const float* __restrict__ pos,
                             const int*   __restrict__ tgt,
                             float* __restrict__ x,
                             float* __restrict__ padmask) {
    int n = blockIdx.x;
    int b = n / L_, l = n % L_;
    int tok = tgt[b * (L_ + 1) + l];
    if (threadIdx.x == 0) padmask[n] = (tok == PAD_ID) ? -1e30f : 0.0f;
    int t = threadIdx.x;  // 128 threads, D/4 = 128 float4
    float4 e  = ((const float4*)(emb   + (size_t)tok * D_))[t];
    float4 p  = ((const float4*)(point + (size_t)b   * D_))[t];
    float4 ps = ((const float4*)(pos   + (size_t)l   * D_))[t];
    float4 o;
    o.x = e.x + p.x + ps.x; o.y = e.y + p.y + ps.y;
    o.z = e.z + p.z + ps.z; o.w = e.w + p.w + ps.w;
    ((float4*)(x + (size_t)n * D_))[t] = o;
}

// ---------------- helpers for tf32 tensor-core GEMM ----------------
__device__ __forceinline__ uint32_t f2tf32(float f) {
    uint32_t u;
    asm("cvt.rna.tf32.f32 %0, %1;" : "=r"(u) : "f"(f));
    return u;
}

__device__ __forceinline__ void mma_tf32(float* c, const uint32_t* a, const uint32_t* b) {
    asm volatile(
        "mma.sync.aligned.m16n8k8.row.col.f32.tf32.tf32.f32 "
        "{%0,%1,%2,%3}, {%4,%5,%6,%7}, {%8,%9}, {%0,%1,%2,%3};"
        : "+f"(c[0]), "+f"(c[1]), "+f"(c[2]), "+f"(c[3])
        : "r"(a[0]), "r"(a[1]), "r"(a[2]), "r"(a[3]), "r"(b[0]), "r"(b[1]));
}

// ---------------- TF32 GEMM: C[N,M] = A[N,K] @ W[M,K]^T + bias, opt relu ----
// Block tile 128x128, BK=32, 128 threads = 4 warps, warp tile 64x64.
// Requires N % 128 == 0, K % 32 == 0. M may be ragged.
// Smem k-major [k][m], stride 136 -> conflict-free staging stores & frag loads.
__global__ __launch_bounds__(128) void tgemm(
    int N, int M, int K, int lda,
    const float* __restrict__ A, const float* __restrict__ W,
    const float* __restrict__ bias, float* __restrict__ C, int relu)
{
    __shared__ uint32_t As[32][136];
    __shared__ uint32_t Bs[32][136];
    const int tid = threadIdx.x;
    const int wid = tid >> 5, lane = tid & 31;
    const int g = lane >> 2, tig = lane & 3;
    const int wm = (wid & 1) * 64;
    const int wn = (wid >> 1) * 64;
    const int bm = blockIdx.y * 128;
    const int bn = blockIdx.x * 128;

    float acc[4][8][4];
#pragma unroll
    for (int i = 0; i < 4; i++)
#pragma unroll
        for (int j = 0; j < 8; j++)
#pragma unroll
            for (int r = 0; r < 4; r++) acc[i][j][r] = 0.f;

    // staging: thread tid owns row tid of both tiles (32 consecutive k each)
    const float* Arow = A + (size_t)(bm + tid) * lda;
    const bool wok = (bn + tid) < M;
    const float* Wrow = W + (size_t)(wok ? (bn + tid) : 0) * K;

    float4 pa[8], pb[8];
#pragma unroll
    for (int q = 0; q < 8; q++) {
        pa[q] = *(const float4*)(Arow + 4 * q);
        pb[q] = wok ? *(const float4*)(Wrow + 4 * q) : make_float4(0.f, 0.f, 0.f, 0.f);
    }

    for (int kt = 0; kt < K; kt += 32) {
        // store staged tile (cvt to tf32 once here)
#pragma unroll
        for (int q = 0; q < 8; q++) {
            As[4 * q + 0][tid] = f2tf32(pa[q].x);
            As[4 * q + 1][tid] = f2tf32(pa[q].y);
            As[4 * q + 2][tid] = f2tf32(pa[q].z);
            As[4 * q + 3][tid] = f2tf32(pa[q].w);
            Bs[4 * q + 0][tid] = f2tf32(pb[q].x);
            Bs[4 * q + 1][tid] = f2tf32(pb[q].y);
            Bs[4 * q + 2][tid] = f2tf32(pb[q].z);
            Bs[4 * q + 3][tid] = f2tf32(pb[q].w);
        }
        __syncthreads();

        // prefetch next k-tile while computing
        if (kt + 32 < K) {
#pragma unroll
            for (int q = 0; q < 8; q++) {
                pa[q] = *(const float4*)(Arow + kt + 32 + 4 * q);
                pb[q] = wok ? *(const float4*)(Wrow + kt + 32 + 4 * q)
                            : make_float4(0.f, 0.f, 0.f, 0.f);
            }
        }

#pragma unroll
        for (int ks = 0; ks < 4; ks++) {
            const int k0 = ks * 8;
            uint32_t af[4][4], bf[8][2];
#pragma unroll
            for (int i = 0; i < 4; i++) {
                af[i][0] = As[k0 + tig][wm + 16 * i + g];
                af[i][1] = As[k0 + tig][wm + 16 * i + g + 8];
                af[i][2] = As[k0 + tig + 4][wm + 16 * i + g];
                af[i][3] = As[k0 + tig + 4][wm + 16 * i + g + 8];
            }
#pragma unroll
            for (int j = 0; j < 8; j++) {
                bf[j][0] = Bs[k0 + tig][wn + 8 * j + g];
                bf[j][1] = Bs[k0 + tig + 4][wn + 8 * j + g];
            }
#pragma unroll
            for (int i = 0; i < 4; i++)
#pragma unroll
                for (int j = 0; j < 8; j++) mma_tf32(acc[i][j], af[i], bf[j]);
        }
        __syncthreads();
    }

    // epilogue
#pragma unroll
    for (int i = 0; i < 4; i++) {
        const int r0 = bm + wm + 16 * i + g;
#pragma unroll
        for (int j = 0; j < 8; j++) {
            const int c0 = bn + wn + 8 * j + 2 * tig;
#pragma unroll
            for (int r = 0; r < 4; r++) {
                const int row = r0 + (r >= 2 ? 8 : 0);
                const int col = c0 + (r & 1);
                if (col < M) {
                    float v = acc[i][j][r] + (bias ? bias[col] : 0.f);
                    if (relu) v = fmaxf(v, 0.f);
                    C[(size_t)row * M + col] = v;
                }
            }
        }
    }
}

// ---------------- causal self-attention, one block per (b, h) ----------------
__global__ __launch_bounds__(64) void attn_kernel(const float* __restrict__ qkv,
                            const float* __restrict__ padmask,
                            float* __restrict__ o) {
    __shared__ float ks[L_][HD_];
    __shared__ float vs[L_][HD_];
    int b = blockIdx.x / NH_, h = blockIdx.x % NH_;
    const float* base = qkv + (size_t)b * L_ * (3 * D_) + h * HD_;
    for (int idx = threadIdx.x; idx < L_ * HD_; idx += 64) {
        int l = idx >> 6, d = idx & 63;
        ks[l][d] = base[(size_t)l * (3 * D_) + D_ + d];
        vs[l][d] = base[(size_t)l * (3 * D_) + 2 * D_ + d];
    }
    __syncthreads();
    int q = threadIdx.x;
    if (q >= L_) return;
    float qr[HD_];
    const float* qrow = base + (size_t)q * (3 * D_);
#pragma unroll
    for (int d = 0; d < HD_; d++) qr[d] = qrow[d];
    float m = -1e30f, lsum = 0.f;
    float acc[HD_];
#pragma unroll
    for (int d = 0; d < HD_; d++) acc[d] = 0.f;
    const float* pm = padmask + b * L_;
    for (int k = 0; k <= q; k++) {
        float s = 0.f;
#pragma unroll
        for (int d = 0; d < HD_; d++) s += qr[d] * ks[k][d];
        s = s * 0.125f + pm[k];
        float mn = fmaxf(m, s);
        float corr = expf(m - mn);
        float e = expf(s - mn);
        lsum = lsum * corr + e;
#pragma unroll
        for (int d = 0; d < HD_; d++) acc[d] = acc[d] * corr + e * vs[k][d];
        m = mn;
    }
    float inv = 1.0f / lsum;
    float* orow = o + (size_t)(b * L_ + q) * D_ + h * HD_;
#pragma unroll
    for (int d = 0; d < HD_; d++) orow[d] = acc[d] * inv;
}

// ---------------- fused residual add + LayerNorm ----------------
__global__ __launch_bounds__(128) void add_ln_kernel(
                              float* __restrict__ x, const float* __restrict__ y, int ybatch,
                              const float* __restrict__ s, const float* __restrict__ b) {
    int n = blockIdx.x;
    float* xr = x + (size_t)n * D_;
    const float* yr = y + (size_t)(ybatch ? (n / L_) : n) * D_;
    int t = threadIdx.x;  // 128
    float4 xv = ((const float4*)xr)[t];
    float4 yv = ((const float4*)yr)[t];
    float v0 = xv.x + yv.x, v1 = xv.y + yv.y, v2 = xv.z + yv.z, v3 = xv.w + yv.w;
    float sum = v0 + v1 + v2 + v3;
    float sq  = v0 * v0 + v1 * v1 + v2 * v2 + v3 * v3;
#pragma unroll
    for (int off = 16; off > 0; off >>= 1) {
        sum += __shfl_xor_sync(0xffffffffu, sum, off);
        sq  += __shfl_xor_sync(0xffffffffu, sq,  off);
    }
    __shared__ float rs[4], rq[4];
    int wid = t >> 5, lane = t & 31;
    if (lane == 0) { rs[wid] = sum; rq[wid] = sq; }
    __syncthreads();
    sum = rs[0] + rs[1] + rs[2] + rs[3];
    sq  = rq[0] + rq[1] + rq[2] + rq[3];
    float mean = sum * (1.0f / D_);
    float var  = sq  * (1.0f / D_) - mean * mean;
    float rstd = rsqrtf(var + 1e-5f);
    float4 sv = ((const float4*)s)[t];
    float4 bv = ((const float4*)b)[t];
    float4 o;
    o.x = (v0 - mean) * rstd * sv.x + bv.x;
    o.y = (v1 - mean) * rstd * sv.y + bv.y;
    o.z = (v2 - mean) * rstd * sv.z + bv.z;
    o.w = (v3 - mean) * rstd * sv.w + bv.w;
    ((float4*)xr)[t] = o;
}

// ---------------- launch ----------------
extern "C" void kernel_launch(void* const* d_in, const int* in_sizes, int n_in,
                              void* d_out, int out_size) {
    const float* encoder_out = (const float*)d_in[0];
    const float* point_out   = (const float*)d_in[1];
    const float* emb         = (const float*)d_in[2];
    const float* pos_embed   = (const float*)d_in[3];
    const float* sa_inw      = (const float*)d_in[4];
    const float* sa_inb      = (const float*)d_in[5];
    const float* sa_outw     = (const float*)d_in[6];
    const float* sa_outb     = (const float*)d_in[7];
    const float* ca_inw      = (const float*)d_in[8];
    const float* ca_inb      = (const float*)d_in[9];
    const float* ca_outw     = (const float*)d_in[10];
    const float* ca_outb     = (const float*)d_in[11];
    const float* ln1_s       = (const float*)d_in[12];
    const float* ln1_b       = (const float*)d_in[13];
    const float* ln2_s       = (const float*)d_in[14];
    const float* ln2_b       = (const float*)d_in[15];
    const float* ln3_s       = (const float*)d_in[16];
    const float* ln3_b       = (const float*)d_in[17];
    const float* ff1_w       = (const float*)d_in[18];
    const float* ff1_b       = (const float*)d_in[19];
    const float* ff2_w       = (const float*)d_in[20];
    const float* ff2_b       = (const float*)d_in[21];
    const float* out_w       = (const float*)d_in[22];
    const float* out_b       = (const float*)d_in[23];
    const int*   tgt         = (const int*)d_in[24];

    float *x, *t, *qkv, *h, *vmem, *yca, *pm;
    cudaGetSymbolAddress((void**)&x,    g_x);
    cudaGetSymbolAddress((void**)&t,    g_t);
    cudaGetSymbolAddress((void**)&qkv,  g_qkv);
    cudaGetSymbolAddress((void**)&h,    g_h);
    cudaGetSymbolAddress((void**)&vmem, g_vmem);
    cudaGetSymbolAddress((void**)&yca,  g_yca);
    cudaGetSymbolAddress((void**)&pm,   g_padmask);

    const int GY = NTOK / 128;  // 122

    embed_kernel<<<NTOK, 128>>>(emb, point_out, pos_embed, tgt, x, pm);

    for (int i = 0; i < NL_; i++) {
        const float* sa_w_i   = sa_inw  + (size_t)i * 3 * D_ * D_;
        const float* sa_b_i   = sa_inb  + (size_t)i * 3 * D_;
        const float* sa_ow_i  = sa_outw + (size_t)i * D_ * D_;
        const float* sa_ob_i  = sa_outb + (size_t)i * D_;
        const float* ca_wv_i  = ca_inw  + (size_t)i * 3 * D_ * D_ + (size_t)2 * D_ * D_;
        const float* ca_bv_i  = ca_inb  + (size_t)i * 3 * D_ + 2 * D_;
        const float* ca_ow_i  = ca_outw + (size_t)i * D_ * D_;
        const float* ca_ob_i  = ca_outb + (size_t)i * D_;
        const float* f1w_i    = ff1_w   + (size_t)i * DFF_ * D_;
        const float* f1b_i    = ff1_b   + (size_t)i * DFF_;
        const float* f2w_i    = ff2_w   + (size_t)i * D_ * DFF_;
        const float* f2b_i    = ff2_b   + (size_t)i * D_;

        // ---- self attention ----
        tgemm<<<dim3(12, GY), 128>>>(NTOK, 3 * D_, D_, D_, x, sa_w_i, sa_b_i, qkv, 0);
        attn_kernel<<<B_ * NH_, 64>>>(qkv, pm, h);
        tgemm<<<dim3(4, GY), 128>>>(NTOK, D_, D_, D_, h, sa_ow_i, sa_ob_i, t, 0);
        add_ln_kernel<<<NTOK, 128>>>(x, t, 0, ln1_s + i * D_, ln1_b + i * D_);

        // ---- cross attention (single memory token -> output is V(mem) @ Wout + b,
        //      constant over query positions; Q/K projections provably irrelevant) ----
        tgemm<<<dim3(4, 2), 128>>>(B_, D_, D_, SENC_ * D_, encoder_out, ca_wv_i, ca_bv_i, vmem, 0);
        tgemm<<<dim3(4, 2), 128>>>(B_, D_, D_, D_, vmem, ca_ow_i, ca_ob_i, yca, 0);
        add_ln_kernel<<<NTOK, 128>>>(x, yca, 1, ln2_s + i * D_, ln2_b + i * D_);

        // ---- FFN ----
        tgemm<<<dim3(16, GY), 128>>>(NTOK, DFF_, D_, D_, x, f1w_i, f1b_i, h, 1);
        tgemm<<<dim3(4, GY), 128>>>(NTOK, D_, DFF_, DFF_, h, f2w_i, f2b_i, t, 0);
        add_ln_kernel<<<NTOK, 128>>>(x, t, 0, ln3_s + i * D_, ln3_b + i * D_);
    }

    // ---- final logits ----
    tgemm<<<dim3((VOCAB + 127) / 128, GY), 128>>>(NTOK, VOCAB, D_, D_, x, out_w, out_b,
                                                  (float*)d_out, 0);
}

// round 8
// speedup vs baseline: 2.0497x; 1.1348x over previous
#include <cuda_runtime.h>
#include <cuda_bf16.h>
#include <cstdint>

#define D_     512
#define NH_    8
#define HD_    64
#define NL_    6
#define DFF_   2048
#define VOCAB  1027
#define PAD_ID 1026
#define B_     256
#define SENC_  16
#define L_     61
#define NTOK   (B_ * L_)   // 15616 = 122 * 128

// ---------------- device scratch ----------------
__device__ float g_x[NTOK * D_];
__device__ float g_t[NTOK * D_];
__device__ float g_qkv[NTOK * 3 * D_];
__device__ float g_h[(size_t)NTOK * DFF_];
__device__ float g_vmem[B_ * D_];
__device__ float g_yca[B_ * D_];
__device__ float g_padmask[NTOK];

// ---------------- helpers ----------------
__device__ __forceinline__ uint32_t smem_u32(const void* p) {
    uint32_t a;
    asm("{ .reg .u64 t; cvta.to.shared.u64 t, %1; cvt.u32.u64 %0, t; }" : "=r"(a) : "l"(p));
    return a;
}
__device__ __forceinline__ uint32_t f2tf32(float f) {
    uint32_t u; asm("cvt.rna.tf32.f32 %0, %1;" : "=r"(u) : "f"(f)); return u;
}
__device__ __forceinline__ void mma_tf32(float* c, const uint32_t* a, const uint32_t* b) {
    asm volatile(
        "mma.sync.aligned.m16n8k8.row.col.f32.tf32.tf32.f32 "
        "{%0,%1,%2,%3}, {%4,%5,%6,%7}, {%8,%9}, {%0,%1,%2,%3};"
        : "+f"(c[0]), "+f"(c[1]), "+f"(c[2]), "+f"(c[3])
        : "r"(a[0]), "r"(a[1]), "r"(a[2]), "r"(a[3]), "r"(b[0]), "r"(b[1]));
}
__device__ __forceinline__ void cp16(uint32_t dst, const void* src, bool ok) {
    int sz = ok ? 16 : 0;
    asm volatile("cp.async.ca.shared.global [%0], [%1], 16, %2;"
                 :: "r"(dst), "l"(src), "r"(sz));
}
#define CP_COMMIT() asm volatile("cp.async.commit_group;" ::: "memory")

// smem geometry (floats): row stride 36, 128 rows per matrix, A then B, 3 stages
#define RS     36
#define ABUF_F (128 * RS)            // 4608 floats
#define STG_F  (2 * ABUF_F)          // 9216 floats per stage (A+B)
#define SM_BYTES (3 * STG_F * 4)     // 110592 bytes

// ---- TF32 GEMM: C[Nrows, M] = A[Nrows, K](lda) @ W[M, K]^T + bias, opt relu
// CTA 128x128, BK=32, 256 threads = 8 warps, warp tile 32x64, cp.async 3-stage.
// Requires Nrows % 128 == 0, K % 64 == 0 (>=2 k-tiles). M ragged OK.
__global__ __launch_bounds__(256, 2) void tgemm(
    int M, int K, int lda,
    const float* __restrict__ A, const float* __restrict__ W,
    const float* __restrict__ bias, float* __restrict__ C, int relu)
{
    extern __shared__ float sm[];
    const uint32_t sb = smem_u32(sm);
    const int tid = threadIdx.x;
    const int wid = tid >> 5, lane = tid & 31;
    const int g = lane >> 2, tig = lane & 3;
    const int wm = (wid & 3) * 32;
    const int wn = (wid >> 2) * 64;
    const int bm = blockIdx.y * 128;
    const int bn = blockIdx.x * 128;

    float acc[2][8][4];
#pragma unroll
    for (int i = 0; i < 2; i++)
#pragma unroll
        for (int j = 0; j < 8; j++)
#pragma unroll
            for (int r = 0; r < 4; r++) acc[i][j][r] = 0.f;

    // staging: thread owns half a row (16 floats) of A and of B
    const int srow = tid >> 1;
    const int shalf = (tid & 1) * 16;
    const float* Asrc = A + (size_t)(bm + srow) * lda + shalf;
    const bool bok = (bn + srow) < M;
    const float* Wsrc = W + (size_t)(bok ? (bn + srow) : 0) * K + shalf;
    const uint32_t adst0 = sb + (uint32_t)(srow * RS + shalf) * 4u;
    const uint32_t bdst0 = adst0 + ABUF_F * 4u;

    const int nblk = K >> 5;

    // prologue: issue stages 0 and 1
#pragma unroll
    for (int st = 0; st < 2; st++) {
        const uint32_t soff = (uint32_t)(st * STG_F) * 4u;
        const int kt = st * 32;
#pragma unroll
        for (int q = 0; q < 4; q++)
            cp16(adst0 + soff + q * 16u, Asrc + kt + q * 4, true);
#pragma unroll
        for (int q = 0; q < 4; q++)
            cp16(bdst0 + soff + q * 16u, Wsrc + kt + q * 4, bok);
        CP_COMMIT();
    }

    int buf = 0;
    for (int b = 0; b < nblk; b++) {
        if (b + 1 < nblk) asm volatile("cp.async.wait_group 1;" ::: "memory");
        else              asm volatile("cp.async.wait_group 0;" ::: "memory");
        __syncthreads();

        // issue stage b+2 (safe: all warps finished reading that buffer's prior life)
        if (b + 2 < nblk) {
            int nb = buf + 2; if (nb >= 3) nb -= 3;
            const uint32_t soff = (uint32_t)(nb * STG_F) * 4u;
            const int kt = (b + 2) * 32;
#pragma unroll
            for (int q = 0; q < 4; q++)
                cp16(adst0 + soff + q * 16u, Asrc + kt + q * 4, true);
#pragma unroll
            for (int q = 0; q < 4; q++)
                cp16(bdst0 + soff + q * 16u, Wsrc + kt + q * 4, bok);
            CP_COMMIT();
        }

        const float* As_ = sm + buf * STG_F;
        const float* Bs_ = As_ + ABUF_F;
#pragma unroll
        for (int ks = 0; ks < 4; ks++) {
            const int k0 = ks * 8;
            uint32_t af[2][4], bf[8][2];
#pragma unroll
            for (int i = 0; i < 2; i++) {
                const int r0 = (wm + 16 * i + g) * RS;
                const int r1 = (wm + 16 * i + g + 8) * RS;
                af[i][0] = f2tf32(As_[r0 + k0 + tig]);
                af[i][1] = f2tf32(As_[r1 + k0 + tig]);
                af[i][2] = f2tf32(As_[r0 + k0 + tig + 4]);
                af[i][3] = f2tf32(As_[r1 + k0 + tig + 4]);
            }
#pragma unroll
            for (int j = 0; j < 8; j++) {
                const int rb = (wn + 8 * j + g) * RS;
                bf[j][0] = f2tf32(Bs_[rb + k0 + tig]);
                bf[j][1] = f2tf32(Bs_[rb + k0 + tig + 4]);
            }
#pragma unroll
            for (int i = 0; i < 2; i++)
#pragma unroll
                for (int j = 0; j < 8; j++) mma_tf32(acc[i][j], af[i], bf[j]);
        }
        buf++; if (buf == 3) buf = 0;
    }

    // epilogue: rows bm+wm+16i+{g, g+8}, cols bn+wn+8j+2*tig+{0,1}
    const bool meven = (M & 1) == 0;  // float2 stores only when every row base is 8B-aligned
#pragma unroll
    for (int i = 0; i < 2; i++) {
        const int r0 = bm + wm + 16 * i + g;
#pragma unroll
        for (int j = 0; j < 8; j++) {
            const int col = bn + wn + 8 * j + 2 * tig;
            const float bz0 = bias ? bias[col < M ? col : 0] : 0.f;
            const float bz1 = bias ? bias[(col + 1) < M ? (col + 1) : 0] : 0.f;
#pragma unroll
            for (int h = 0; h < 2; h++) {
                const int row = r0 + h * 8;
                float v0 = acc[i][j][2 * h + 0] + bz0;
                float v1 = acc[i][j][2 * h + 1] + bz1;
                if (relu) { v0 = fmaxf(v0, 0.f); v1 = fmaxf(v1, 0.f); }
                float* cp = C + (size_t)row * M + col;
                if (col + 1 < M) {
                    if (meven) { float2 o = make_float2(v0, v1); *(float2*)cp = o; }
                    else       { cp[0] = v0; cp[1] = v1; }
                } else if (col < M) {
                    *cp = v0;
                }
            }
        }
    }
}

// ---------------- embedding + mask ----------------
__global__ void embed_kernel(const float* __restrict__ emb,
                             const float* __restrict__ point,
                             const float* __restrict__ pos,
                             const int*   __restrict__ tgt,
                             float* __restrict__ x,
                             float* __restrict__ padmask) {
    int n = blockIdx.x;
    int b = n / L_, l = n % L_;
    int tok = tgt[b * (L_ + 1) + l];
    if (threadIdx.x == 0) padmask[n] = (tok == PAD_ID) ? -1e30f : 0.0f;
    int t = threadIdx.x;
    float4 e  = ((const float4*)(emb   + (size_t)tok * D_))[t];
    float4 p  = ((const float4*)(point + (size_t)b   * D_))[t];
    float4 ps = ((const float4*)(pos   + (size_t)l   * D_))[t];
    float4 o;
    o.x = e.x + p.x + ps.x; o.y = e.y + p.y + ps.y;
    o.z = e.z + p.z + ps.z; o.w = e.w + p.w + ps.w;
    ((float4*)(x + (size_t)n * D_))[t] = o;
}

// ---------------- causal self-attention, one block per (b, h) ----------------
__global__ __launch_bounds__(64) void attn_kernel(const float* __restrict__ qkv,
                            const float* __restrict__ padmask,
                            float* __restrict__ o) {
    __shared__ float ks[L_][HD_];
    __shared__ float vs[L_][HD_];
    int b = blockIdx.x / NH_, h = blockIdx.x % NH_;
    const float* base = qkv + (size_t)b * L_ * (3 * D_) + h * HD_;
    for (int idx = threadIdx.x; idx < L_ * HD_; idx += 64) {
        int l = idx >> 6, d = idx & 63;
        ks[l][d] = base[(size_t)l * (3 * D_) + D_ + d];
        vs[l][d] = base[(size_t)l * (3 * D_) + 2 * D_ + d];
    }
    __syncthreads();
    int q = threadIdx.x;
    if (q >= L_) return;
    float qr[HD_];
    const float* qrow = base + (size_t)q * (3 * D_);
#pragma unroll
    for (int d = 0; d < HD_; d++) qr[d] = qrow[d];
    float m = -1e30f, lsum = 0.f;
    float acc[HD_];
#pragma unroll
    for (int d = 0; d < HD_; d++) acc[d] = 0.f;
    const float* pm = padmask + b * L_;
    for (int k = 0; k <= q; k++) {
        float s = 0.f;
#pragma unroll
        for (int d = 0; d < HD_; d++) s += qr[d] * ks[k][d];
        s = s * 0.125f + pm[k];
        float mn = fmaxf(m, s);
        float corr = expf(m - mn);
        float e = expf(s - mn);
        lsum = lsum * corr + e;
#pragma unroll
        for (int d = 0; d < HD_; d++) acc[d] = acc[d] * corr + e * vs[k][d];
        m = mn;
    }
    float inv = 1.0f / lsum;
    float* orow = o + (size_t)(b * L_ + q) * D_ + h * HD_;
#pragma unroll
    for (int d = 0; d < HD_; d++) orow[d] = acc[d] * inv;
}

// ---------------- fused residual add + LayerNorm ----------------
__global__ __launch_bounds__(128) void add_ln_kernel(
                              float* __restrict__ x, const float* __restrict__ y, int ybatch,
                              const float* __restrict__ s, const float* __restrict__ b) {
    int n = blockIdx.x;
    float* xr = x + (size_t)n * D_;
    const float* yr = y + (size_t)(ybatch ? (n / L_) : n) * D_;
    int t = threadIdx.x;
    float4 xv = ((const float4*)xr)[t];
    float4 yv = ((const float4*)yr)[t];
    float v0 = xv.x + yv.x, v1 = xv.y + yv.y, v2 = xv.z + yv.z, v3 = xv.w + yv.w;
    float sum = v0 + v1 + v2 + v3;
    float sq  = v0 * v0 + v1 * v1 + v2 * v2 + v3 * v3;
#pragma unroll
    for (int off = 16; off > 0; off >>= 1) {
        sum += __shfl_xor_sync(0xffffffffu, sum, off);
        sq  += __shfl_xor_sync(0xffffffffu, sq,  off);
    }
    __shared__ float rs[4], rq[4];
    int wid = t >> 5, lane = t & 31;
    if (lane == 0) { rs[wid] = sum; rq[wid] = sq; }
    __syncthreads();
    sum = rs[0] + rs[1] + rs[2] + rs[3];
    sq  = rq[0] + rq[1] + rq[2] + rq[3];
    float mean = sum * (1.0f / D_);
    float var  = sq  * (1.0f / D_) - mean * mean;
    float rstd = rsqrtf(var + 1e-5f);
    float4 sv = ((const float4*)s)[t];
    float4 bv = ((const float4*)b)[t];
    float4 o;
    o.x = (v0 - mean) * rstd * sv.x + bv.x;
    o.y = (v1 - mean) * rstd * sv.y + bv.y;
    o.z = (v2 - mean) * rstd * sv.z + bv.z;
    o.w = (v3 - mean) * rstd * sv.w + bv.w;
    ((float4*)xr)[t] = o;
}

// ---------------- launch ----------------
static inline void launch_gemm(int Nrows, int M, int K, int lda,
                               const float* A, const float* W,
                               const float* bias, float* C, int relu) {
    dim3 g((M + 127) / 128, Nrows / 128);
    tgemm<<<g, 256, SM_BYTES>>>(M, K, lda, A, W, bias, C, relu);
}

extern "C" void kernel_launch(void* const* d_in, const int* in_sizes, int n_in,
                              void* d_out, int out_size) {
    const float* encoder_out = (const float*)d_in[0];
    const float* point_out   = (const float*)d_in[1];
    const float* emb         = (const float*)d_in[2];
    const float* pos_embed   = (const float*)d_in[3];
    const float* sa_inw      = (const float*)d_in[4];
    const float* sa_inb      = (const float*)d_in[5];
    const float* sa_outw     = (const float*)d_in[6];
    const float* sa_outb     = (const float*)d_in[7];
    const float* ca_inw      = (const float*)d_in[8];
    const float* ca_inb      = (const float*)d_in[9];
    const float* ca_outw     = (const float*)d_in[10];
    const float* ca_outb     = (const float*)d_in[11];
    const float* ln1_s       = (const float*)d_in[12];
    const float* ln1_b       = (const float*)d_in[13];
    const float* ln2_s       = (const float*)d_in[14];
    const float* ln2_b       = (const float*)d_in[15];
    const float* ln3_s       = (const float*)d_in[16];
    const float* ln3_b       = (const float*)d_in[17];
    const float* ff1_w       = (const float*)d_in[18];
    const float* ff1_b       = (const float*)d_in[19];
    const float* ff2_w       = (const float*)d_in[20];
    const float* ff2_b       = (const float*)d_in[21];
    const float* out_w       = (const float*)d_in[22];
    const float* out_b       = (const float*)d_in[23];
    const int*   tgt         = (const int*)d_in[24];

    cudaFuncSetAttribute(tgemm, cudaFuncAttributeMaxDynamicSharedMemorySize, SM_BYTES);

    float *x, *t, *qkv, *h, *vmem, *yca, *pm;
    cudaGetSymbolAddress((void**)&x,    g_x);
    cudaGetSymbolAddress((void**)&t,    g_t);
    cudaGetSymbolAddress((void**)&qkv,  g_qkv);
    cudaGetSymbolAddress((void**)&h,    g_h);
    cudaGetSymbolAddress((void**)&vmem, g_vmem);
    cudaGetSymbolAddress((void**)&yca,  g_yca);
    cudaGetSymbolAddress((void**)&pm,   g_padmask);

    embed_kernel<<<NTOK, 128>>>(emb, point_out, pos_embed, tgt, x, pm);

    for (int i = 0; i < NL_; i++) {
        const float* sa_w_i   = sa_inw  + (size_t)i * 3 * D_ * D_;
        const float* sa_b_i   = sa_inb  + (size_t)i * 3 * D_;
        const float* sa_ow_i  = sa_outw + (size_t)i * D_ * D_;
        const float* sa_ob_i  = sa_outb + (size_t)i * D_;
        const float* ca_wv_i  = ca_inw  + (size_t)i * 3 * D_ * D_ + (size_t)2 * D_ * D_;
        const float* ca_bv_i  = ca_inb  + (size_t)i * 3 * D_ + 2 * D_;
        const float* ca_ow_i  = ca_outw + (size_t)i * D_ * D_;
        const float* ca_ob_i  = ca_outb + (size_t)i * D_;
        const float* f1w_i    = ff1_w   + (size_t)i * DFF_ * D_;
        const float* f1b_i    = ff1_b   + (size_t)i * DFF_;
        const float* f2w_i    = ff2_w   + (size_t)i * D_ * DFF_;
        const float* f2b_i    = ff2_b   + (size_t)i * D_;

        // ---- self attention ----
        launch_gemm(NTOK, 3 * D_, D_, D_, x, sa_w_i, sa_b_i, qkv, 0);
        attn_kernel<<<B_ * NH_, 64>>>(qkv, pm, h);
        launch_gemm(NTOK, D_, D_, D_, h, sa_ow_i, sa_ob_i, t, 0);
        add_ln_kernel<<<NTOK, 128>>>(x, t, 0, ln1_s + i * D_, ln1_b + i * D_);

        // ---- cross attention (single memory token: output = V(mem) @ Wout + b,
        //      constant over query positions; Q/K provably irrelevant) ----
        launch_gemm(B_, D_, D_, SENC_ * D_, encoder_out, ca_wv_i, ca_bv_i, vmem, 0);
        launch_gemm(B_, D_, D_, D_, vmem, ca_ow_i, ca_ob_i, yca, 0);
        add_ln_kernel<<<NTOK, 128>>>(x, yca, 1, ln2_s + i * D_, ln2_b + i * D_);

        // ---- FFN ----
        launch_gemm(NTOK, DFF_, D_, D_, x, f1w_i, f1b_i, h, 1);
        launch_gemm(NTOK, D_, DFF_, DFF_, h, f2w_i, f2b_i, t, 0);
        add_ln_kernel<<<NTOK, 128>>>(x, t, 0, ln3_s + i * D_, ln3_b + i * D_);
    }

    // ---- final logits ----
    launch_gemm(NTOK, VOCAB, D_, D_, x, out_w, out_b, (float*)d_out, 0);
}